// round 6
// baseline (speedup 1.0000x reference)
#include <cuda_runtime.h>

#define OBS_DIM   256
#define HID_DIM   512
#define ACT_DIM   18
#define BATCH     1024
#define ETA       0.01f
#define LAMBDA    0.95f
#define BPB       16     // batches per block

__global__ void q_init_kernel(const float* __restrict__ bq, float* __restrict__ q) {
    int i = blockIdx.x * blockDim.x + threadIdx.x;
    if (i < BATCH * ACT_DIM) q[i] = bq[i % ACT_DIM];
}

__device__ __forceinline__ float tanh_approx(float x) {
    float r;
    asm("tanh.approx.f32 %0, %1;" : "=f"(r) : "f"(x));
    return r;
}

// Fused MPN step + Hebbian update + q-head. R3 skeleton (register-resident
// M rows + register prefetch — measured fastest memory path), with the
// software tanhf replaced by the single-MUFU tanh.approx to shorten the
// allreduce->store dependency tail and cut register pressure.
__global__ __launch_bounds__(256, 7) void mpn_step_kernel(
    const float* __restrict__ obs,
    const float* __restrict__ M,
    const float* __restrict__ W,
    const float* __restrict__ bh,
    const float* __restrict__ Wq,
    float* __restrict__ newM,
    float* __restrict__ q)
{
    __shared__ float4 xs[BPB * OBS_DIM / 4];  // 16 obs rows: 16 KB
    __shared__ float  hsh[BPB][8];            // hv per (batch, warp)

    const int b0    = blockIdx.y * BPB;
    const int hbase = blockIdx.x * 8;
    const int tid   = threadIdx.x;

    // 16 obs rows = 1024 float4: four per thread.
    {
        const float4* og = reinterpret_cast<const float4*>(obs + (size_t)b0 * OBS_DIM);
        xs[tid]       = og[tid];
        xs[tid + 256] = og[tid + 256];
        xs[tid + 512] = og[tid + 512];
        xs[tid + 768] = og[tid + 768];
    }
    __syncthreads();

    const int warp = tid >> 5;
    const int lane = tid & 31;
    const int h    = hbase + warp;

    const float bias = __ldg(bh + h);
    const float4* wp = reinterpret_cast<const float4*>(W + (size_t)h * OBS_DIM);
    const float4 w0  = __ldg(wp + lane);
    const float4 w1  = __ldg(wp + lane + 32);

    const size_t bstride = (size_t)HID_DIM * OBS_DIM / 4;  // float4 units
    const float4* Mrow = reinterpret_cast<const float4*>(M)
                       + ((size_t)b0 * HID_DIM + h) * (OBS_DIM / 4);
    float4* Orow = reinterpret_cast<float4*>(newM)
                 + ((size_t)b0 * HID_DIM + h) * (OBS_DIM / 4);

    // Prologue: loads for iteration 0.
    float4 m0 = __ldcs(Mrow + lane);
    float4 m1 = __ldcs(Mrow + lane + 32);

    #pragma unroll
    for (int i = 0; i < BPB; i++) {
        // Prefetch next batch's M row before the dependency chain.
        float4 p0, p1;
        if (i + 1 < BPB) {
            const float4* Mn = Mrow + (size_t)(i + 1) * bstride;
            p0 = __ldcs(Mn + lane);
            p1 = __ldcs(Mn + lane + 32);
        }

        const float4 x0 = xs[i * 64 + lane];
        const float4 x1 = xs[i * 64 + lane + 32];

        // sum_o W[h,o] * obs[b,o] * (1 + M[b,h,o])
        float acc =
            w0.x * x0.x * (1.0f + m0.x) + w0.y * x0.y * (1.0f + m0.y) +
            w0.z * x0.z * (1.0f + m0.z) + w0.w * x0.w * (1.0f + m0.w) +
            w1.x * x1.x * (1.0f + m1.x) + w1.y * x1.y * (1.0f + m1.y) +
            w1.z * x1.z * (1.0f + m1.z) + w1.w * x1.w * (1.0f + m1.w);

        #pragma unroll
        for (int o = 16; o; o >>= 1)
            acc += __shfl_xor_sync(0xffffffffu, acc, o);

        const float hv = tanh_approx(acc + bias);
        const float eh = ETA * hv;

        float4 n0, n1;
        n0.x = LAMBDA * m0.x + eh * x0.x;  n0.y = LAMBDA * m0.y + eh * x0.y;
        n0.z = LAMBDA * m0.z + eh * x0.z;  n0.w = LAMBDA * m0.w + eh * x0.w;
        n1.x = LAMBDA * m1.x + eh * x1.x;  n1.y = LAMBDA * m1.y + eh * x1.y;
        n1.z = LAMBDA * m1.z + eh * x1.z;  n1.w = LAMBDA * m1.w + eh * x1.w;

        float4* Ob = Orow + (size_t)i * bstride;
        __stcs(Ob + lane,      n0);
        __stcs(Ob + lane + 32, n1);

        if (lane == 0) hsh[i][warp] = hv;

        m0 = p0; m1 = p1;
    }

    __syncthreads();

    // q-head epilogue: warp 0 reduces the block's 8 h-rows, 18 REDs per batch.
    if (warp == 0 && lane < ACT_DIM) {
        const float4* wq = reinterpret_cast<const float4*>(
            Wq + (size_t)lane * HID_DIM + hbase);
        const float4 a0 = __ldg(wq);
        const float4 a1 = __ldg(wq + 1);
        #pragma unroll
        for (int i = 0; i < BPB; i++) {
            float qv = a0.x * hsh[i][0] + a0.y * hsh[i][1]
                     + a0.z * hsh[i][2] + a0.w * hsh[i][3]
                     + a1.x * hsh[i][4] + a1.y * hsh[i][5]
                     + a1.z * hsh[i][6] + a1.w * hsh[i][7];
            atomicAdd(q + (size_t)(b0 + i) * ACT_DIM + lane, qv);
        }
    }
}

extern "C" void kernel_launch(void* const* d_in, const int* in_sizes, int n_in,
                              void* d_out, int out_size) {
    const float* obs = (const float*)d_in[0];  // [1024, 256]
    const float* M   = (const float*)d_in[1];  // [1024, 512, 256]
    const float* W   = (const float*)d_in[2];  // [512, 256]
    const float* bh  = (const float*)d_in[3];  // [512]
    const float* Wq  = (const float*)d_in[4];  // [18, 512]
    const float* bq  = (const float*)d_in[5];  // [18]

    float* q    = (float*)d_out;               // [1024, 18]
    float* newM = q + (size_t)BATCH * ACT_DIM; // [1024, 512, 256]

    q_init_kernel<<<(BATCH * ACT_DIM + 255) / 256, 256>>>(bq, q);

    dim3 grid(HID_DIM / 8, BATCH / BPB);
    mpn_step_kernel<<<grid, 256>>>(obs, M, W, bh, Wq, newM, q);
}

// round 7
// speedup vs baseline: 1.2712x; 1.2712x over previous
#include <cuda_runtime.h>

#define OBS_DIM   256
#define HID_DIM   512
#define ACT_DIM   18
#define BATCH     1024
#define ETA       0.01f
#define LAMBDA    0.95f

__global__ void q_init_kernel(const float* __restrict__ bq, float* __restrict__ q) {
    int i = blockIdx.x * blockDim.x + threadIdx.x;
    if (i < BATCH * ACT_DIM) q[i] = bq[i % ACT_DIM];
}

__device__ __forceinline__ float tanh_approx(float x) {
    float r;
    asm("tanh.approx.f32 %0, %1;" : "=f"(r) : "f"(x));
    return r;
}

// Fused MPN step + Hebbian update + q-head, R1 dataflow: one (batch, 8 h-rows)
// per block, each warp a single independent load->reduce->store chain. No
// loop-carried deps; occupancy supplies the MLP (measured 6.9 TB/s in R1).
// Grid is batch-major so ~1024 consecutive blocks reuse the same 8KB W slice
// from L1, collapsing W's L2 traffic (~512MB -> ~4MB). q-head contributions
// are block-reduced through smem: 18 REDs per block.
__global__ __launch_bounds__(256) void mpn_step_kernel(
    const float* __restrict__ obs,
    const float* __restrict__ M,
    const float* __restrict__ W,
    const float* __restrict__ bh,
    const float* __restrict__ Wq,
    float* __restrict__ newM,
    float* __restrict__ q)
{
    __shared__ float4 xs[OBS_DIM / 4];  // obs row: 1 KB
    __shared__ float  hsh[8];           // hv per warp

    const int b     = blockIdx.x;       // batch-major: W stays L1-hot
    const int hbase = blockIdx.y * 8;
    const int tid   = threadIdx.x;

    if (tid < 64)
        xs[tid] = reinterpret_cast<const float4*>(obs + (size_t)b * OBS_DIM)[tid];
    __syncthreads();

    const int warp = tid >> 5;
    const int lane = tid & 31;
    const int h    = hbase + warp;

    const float4* wp = reinterpret_cast<const float4*>(W + (size_t)h * OBS_DIM);
    const float4* Mrow = reinterpret_cast<const float4*>(
        M + ((size_t)b * HID_DIM + h) * OBS_DIM);

    // Independent loads, issued back-to-back: M streams (evict-first), W L1-hot.
    const float4 m0 = __ldcs(Mrow + lane);
    const float4 m1 = __ldcs(Mrow + lane + 32);
    const float4 w0 = __ldg(wp + lane);
    const float4 w1 = __ldg(wp + lane + 32);
    const float4 x0 = xs[lane];
    const float4 x1 = xs[lane + 32];

    // sum_o W[h,o] * obs[b,o] * (1 + M[b,h,o])
    float acc =
        w0.x * x0.x * (1.0f + m0.x) + w0.y * x0.y * (1.0f + m0.y) +
        w0.z * x0.z * (1.0f + m0.z) + w0.w * x0.w * (1.0f + m0.w) +
        w1.x * x1.x * (1.0f + m1.x) + w1.y * x1.y * (1.0f + m1.y) +
        w1.z * x1.z * (1.0f + m1.z) + w1.w * x1.w * (1.0f + m1.w);

    #pragma unroll
    for (int o = 16; o; o >>= 1)
        acc += __shfl_xor_sync(0xffffffffu, acc, o);

    const float hv = tanh_approx(acc + __ldg(bh + h));
    const float eh = ETA * hv;

    float4 n0, n1;
    n0.x = LAMBDA * m0.x + eh * x0.x;  n0.y = LAMBDA * m0.y + eh * x0.y;
    n0.z = LAMBDA * m0.z + eh * x0.z;  n0.w = LAMBDA * m0.w + eh * x0.w;
    n1.x = LAMBDA * m1.x + eh * x1.x;  n1.y = LAMBDA * m1.y + eh * x1.y;
    n1.z = LAMBDA * m1.z + eh * x1.z;  n1.w = LAMBDA * m1.w + eh * x1.w;

    float4* out = reinterpret_cast<float4*>(
        newM + ((size_t)b * HID_DIM + h) * OBS_DIM);
    __stcs(out + lane,      n0);
    __stcs(out + lane + 32, n1);

    if (lane == 0) hsh[warp] = hv;
    __syncthreads();

    // q-head epilogue: warp 0 reduces this block's 8 h-rows, 18 REDs total.
    if (warp == 0 && lane < ACT_DIM) {
        const float4* wq = reinterpret_cast<const float4*>(
            Wq + (size_t)lane * HID_DIM + hbase);
        const float4 a0 = __ldg(wq);      // L1-hot: same hbase for ~1024 blocks
        const float4 a1 = __ldg(wq + 1);
        const float qv = a0.x * hsh[0] + a0.y * hsh[1]
                       + a0.z * hsh[2] + a0.w * hsh[3]
                       + a1.x * hsh[4] + a1.y * hsh[5]
                       + a1.z * hsh[6] + a1.w * hsh[7];
        atomicAdd(q + (size_t)b * ACT_DIM + lane, qv);
    }
}

extern "C" void kernel_launch(void* const* d_in, const int* in_sizes, int n_in,
                              void* d_out, int out_size) {
    const float* obs = (const float*)d_in[0];  // [1024, 256]
    const float* M   = (const float*)d_in[1];  // [1024, 512, 256]
    const float* W   = (const float*)d_in[2];  // [512, 256]
    const float* bh  = (const float*)d_in[3];  // [512]
    const float* Wq  = (const float*)d_in[4];  // [18, 512]
    const float* bq  = (const float*)d_in[5];  // [18]

    float* q    = (float*)d_out;               // [1024, 18]
    float* newM = q + (size_t)BATCH * ACT_DIM; // [1024, 512, 256]

    q_init_kernel<<<(BATCH * ACT_DIM + 255) / 256, 256>>>(bq, q);

    dim3 grid(BATCH, HID_DIM / 8);             // batch-major for W reuse
    mpn_step_kernel<<<grid, 256>>>(obs, M, W, bh, Wq, newM, q);
}

// round 8
// speedup vs baseline: 1.2814x; 1.0080x over previous
#include <cuda_runtime.h>

#define OBS_DIM   256
#define HID_DIM   512
#define ACT_DIM   18
#define BATCH     1024
#define ETA       0.01f
#define LAMBDA    0.95f

__global__ void q_init_kernel(const float* __restrict__ bq, float* __restrict__ q) {
    int i = blockIdx.x * blockDim.x + threadIdx.x;
    if (i < BATCH * ACT_DIM) q[i] = bq[i % ACT_DIM];
}

__device__ __forceinline__ float tanh_approx(float x) {
    float r;
    asm("tanh.approx.f32 %0, %1;" : "=f"(r) : "f"(x));
    return r;
}

// Fused MPN step + Hebbian update + q-head. One (batch, 8 h-rows) per block;
// each warp is a fully independent load->reduce->store chain from its first
// instruction: obs/W/Wq come straight from L1/L2 via __ldg (obs is 1MB total,
// L2-resident; W slice shared by the whole wave), so there is NO entry
// barrier. The only barrier is the q-head epilogue, split arrive/sync so
// warps 1-7 retire immediately after their M stores.
__global__ __launch_bounds__(256) void mpn_step_kernel(
    const float* __restrict__ obs,
    const float* __restrict__ M,
    const float* __restrict__ W,
    const float* __restrict__ bh,
    const float* __restrict__ Wq,
    float* __restrict__ newM,
    float* __restrict__ q)
{
    __shared__ float hsh[8];            // hv per warp

    const int b     = blockIdx.x;       // batch-major: W stays L1-hot per wave
    const int hbase = blockIdx.y * 8;
    const int tid   = threadIdx.x;
    const int warp  = tid >> 5;
    const int lane  = tid & 31;
    const int h     = hbase + warp;

    const float4* xp = reinterpret_cast<const float4*>(obs + (size_t)b * OBS_DIM);
    const float4* wp = reinterpret_cast<const float4*>(W + (size_t)h * OBS_DIM);
    const float4* Mrow = reinterpret_cast<const float4*>(
        M + ((size_t)b * HID_DIM + h) * OBS_DIM);

    // Independent loads, issued back-to-back: M streams (evict-first),
    // W/obs cache-resident.
    const float4 m0 = __ldcs(Mrow + lane);
    const float4 m1 = __ldcs(Mrow + lane + 32);
    const float4 w0 = __ldg(wp + lane);
    const float4 w1 = __ldg(wp + lane + 32);
    const float4 x0 = __ldg(xp + lane);
    const float4 x1 = __ldg(xp + lane + 32);

    // sum_o W[h,o] * obs[b,o] * (1 + M[b,h,o])
    float acc =
        w0.x * x0.x * (1.0f + m0.x) + w0.y * x0.y * (1.0f + m0.y) +
        w0.z * x0.z * (1.0f + m0.z) + w0.w * x0.w * (1.0f + m0.w) +
        w1.x * x1.x * (1.0f + m1.x) + w1.y * x1.y * (1.0f + m1.y) +
        w1.z * x1.z * (1.0f + m1.z) + w1.w * x1.w * (1.0f + m1.w);

    #pragma unroll
    for (int o = 16; o; o >>= 1)
        acc += __shfl_xor_sync(0xffffffffu, acc, o);

    const float hv = tanh_approx(acc + __ldg(bh + h));
    const float eh = ETA * hv;

    float4 n0, n1;
    n0.x = LAMBDA * m0.x + eh * x0.x;  n0.y = LAMBDA * m0.y + eh * x0.y;
    n0.z = LAMBDA * m0.z + eh * x0.z;  n0.w = LAMBDA * m0.w + eh * x0.w;
    n1.x = LAMBDA * m1.x + eh * x1.x;  n1.y = LAMBDA * m1.y + eh * x1.y;
    n1.z = LAMBDA * m1.z + eh * x1.z;  n1.w = LAMBDA * m1.w + eh * x1.w;

    float4* out = reinterpret_cast<float4*>(
        newM + ((size_t)b * HID_DIM + h) * OBS_DIM);
    __stcs(out + lane,      n0);
    __stcs(out + lane + 32, n1);

    if (lane == 0) hsh[warp] = hv;

    if (warp != 0) {
        // Producers: signal and retire. No blocking wait.
        asm volatile("bar.arrive 1, 256;");
        return;
    }
    asm volatile("bar.sync 1, 256;");

    // q-head epilogue: warp 0 reduces this block's 8 h-rows, 18 REDs total.
    if (lane < ACT_DIM) {
        const float4* wq = reinterpret_cast<const float4*>(
            Wq + (size_t)lane * HID_DIM + hbase);
        const float4 a0 = __ldg(wq);      // L1-hot: same hbase for the wave
        const float4 a1 = __ldg(wq + 1);
        const float qv = a0.x * hsh[0] + a0.y * hsh[1]
                       + a0.z * hsh[2] + a0.w * hsh[3]
                       + a1.x * hsh[4] + a1.y * hsh[5]
                       + a1.z * hsh[6] + a1.w * hsh[7];
        atomicAdd(q + (size_t)b * ACT_DIM + lane, qv);
    }
}

extern "C" void kernel_launch(void* const* d_in, const int* in_sizes, int n_in,
                              void* d_out, int out_size) {
    const float* obs = (const float*)d_in[0];  // [1024, 256]
    const float* M   = (const float*)d_in[1];  // [1024, 512, 256]
    const float* W   = (const float*)d_in[2];  // [512, 256]
    const float* bh  = (const float*)d_in[3];  // [512]
    const float* Wq  = (const float*)d_in[4];  // [18, 512]
    const float* bq  = (const float*)d_in[5];  // [18]

    float* q    = (float*)d_out;               // [1024, 18]
    float* newM = q + (size_t)BATCH * ACT_DIM; // [1024, 512, 256]

    q_init_kernel<<<(BATCH * ACT_DIM + 255) / 256, 256>>>(bq, q);

    dim3 grid(BATCH, HID_DIM / 8);             // batch-major for W reuse
    mpn_step_kernel<<<grid, 256>>>(obs, M, W, bh, Wq, newM, q);
}